// round 17
// baseline (speedup 1.0000x reference)
#include <cuda_runtime.h>
#include <cuda_bf16.h>
#include <cstdint>

#define Bn 16
#define Nn 1024

// Scratch (device globals; no allocation allowed)
__device__ __align__(128) float g_S3[Bn * Nn * 32];    // sum_e (x@W0+b0)  [row][c]
__device__ __align__(128) float g_dis[Bn * Nn * 3];    // deg^-1/2         [row][e]
__device__ __align__(128) __nv_bfloat16 g_adjbf[(size_t)Bn * 3 * Nn * Nn];  // [b][e][n][m]
__device__ __align__(128) __nv_bfloat16 g_saggbf[(size_t)Bn * 3 * Nn * 32]; // [b][e][m][c]

#define CPASYNC16(dst, src) \
    asm volatile("cp.async.cg.shared.global [%0], [%1], 16;" :: "r"(dst), "l"(src))
#define CP_COMMIT() asm volatile("cp.async.commit_group;" ::: "memory")
#define CP_WAIT1()  asm volatile("cp.async.wait_group 1;" ::: "memory")
#define CP_WAIT0()  asm volatile("cp.async.wait_group 0;" ::: "memory")

__device__ __forceinline__ uint32_t sptr(const void* p) {
    return (uint32_t)__cvta_generic_to_shared(p);
}
__device__ __forceinline__ uint32_t pk2(float a, float b) {
    __nv_bfloat162 h = __floats2bfloat162_rn(a, b);
    return *(uint32_t*)&h;
}

// ---------------------------------------------------------------------------
// Kernel 1 (fused): degrees + linears + bf16 deinterleave.
// One block (128 thr) per (b,n) row.  Thread reads 6 CONSECUTIVE float4
// (k' = 24t..24t+23): e of component j of float4 s is (s+j)%3 compile-time,
// and per e the thread owns m = 8t..8t+7 -> one STG.128 of bf16x8 per e.
// Epilogue: dis, saggbf (bf16 dis*(x@W)), S3 = sum_e (x@W0+b0).
// ---------------------------------------------------------------------------
__global__ __launch_bounds__(128) void deg_kernel(
    const float* __restrict__ adj, const float* __restrict__ x,
    const float* __restrict__ W, const float* __restrict__ W0,
    const float* __restrict__ b0)
{
    int row = blockIdx.x;                    // b*N + n
    int b = row >> 10, n = row & 1023;
    const float4* base = (const float4*)(adj + (size_t)row * 3072);
    int t = threadIdx.x;

    __shared__ float xsh[32];
    if (t < 32) xsh[t] = x[(size_t)row * 32 + t];

    float4 v0 = base[6 * t    ];
    float4 v1 = base[6 * t + 1];
    float4 v2 = base[6 * t + 2];
    float4 v3 = base[6 * t + 3];
    float4 v4 = base[6 * t + 4];
    float4 v5 = base[6 * t + 5];

    float s0 = v0.x + v0.w + v1.z + v2.y + v3.x + v3.w + v4.z + v5.y;
    float s1 = v0.y + v1.x + v1.w + v2.z + v3.y + v4.x + v4.w + v5.z;
    float s2 = v0.z + v1.y + v2.x + v2.w + v3.z + v4.y + v5.x + v5.w;

    {
        size_t mo = (size_t)(8 * t);
        uint4 u;
        u.x = pk2(v0.x, v0.w); u.y = pk2(v1.z, v2.y);
        u.z = pk2(v3.x, v3.w); u.w = pk2(v4.z, v5.y);
        *(uint4*)(g_adjbf + (((size_t)(b * 3 + 0) << 10 | n) << 10) + mo) = u;
        u.x = pk2(v0.y, v1.x); u.y = pk2(v1.w, v2.z);
        u.z = pk2(v3.y, v4.x); u.w = pk2(v4.w, v5.z);
        *(uint4*)(g_adjbf + (((size_t)(b * 3 + 1) << 10 | n) << 10) + mo) = u;
        u.x = pk2(v0.z, v1.y); u.y = pk2(v2.x, v2.w);
        u.z = pk2(v3.z, v4.y); u.w = pk2(v5.x, v5.w);
        *(uint4*)(g_adjbf + (((size_t)(b * 3 + 2) << 10 | n) << 10) + mo) = u;
    }

#pragma unroll
    for (int off = 16; off; off >>= 1) {
        s0 += __shfl_down_sync(0xffffffffu, s0, off);
        s1 += __shfl_down_sync(0xffffffffu, s1, off);
        s2 += __shfl_down_sync(0xffffffffu, s2, off);
    }
    __shared__ float red[4][3];
    __shared__ float dis_s[3];
    __shared__ float sS[96];
    int w = t >> 5, lane = t & 31;
    if (lane == 0) { red[w][0] = s0; red[w][1] = s1; red[w][2] = s2; }
    __syncthreads();
    if (t < 3) {
        float tot = red[0][t] + red[1][t] + red[2][t] + red[3][t];
        float d = rsqrtf(fmaxf(tot, 1.0f));
        dis_s[t] = d;
        g_dis[(size_t)row * 3 + t] = d;
    }
    __syncthreads();

    if (t < 96) {
        int e = t >> 5, c = t & 31;
        float a = 0.f, a0 = 0.f;
#pragma unroll
        for (int k = 0; k < 32; k++) {
            float xv = xsh[k];
            a  += xv * __ldg(W  + k * 96 + t);
            a0 += xv * __ldg(W0 + k * 96 + t);
        }
        sS[t] = a0 + __ldg(b0 + t);
        g_saggbf[(((size_t)(b * 3 + e) << 10 | n) << 5) + c] =
            __float2bfloat16(dis_s[e] * a);
    }
    __syncthreads();
    if (t < 32) g_S3[(size_t)row * 32 + t] = sS[t] + sS[32 + t] + sS[64 + t];
}

// ---------------------------------------------------------------------------
// Kernel 2: aggregation as e-SPLIT bf16 tensor GEMM partials.
// Grid (Nn/32, Bn, 3): block handles ONE e-plane (8 chunks of k=128) ->
// 1536 blocks (~10/SM, ~41 warps/SM: latency hidden).
//   P_e[n][c] = sum_m adjbf[b][e][n][m] * saggbf[b][e][m][c]   (fp32 accum)
// Epilogue: out += dis[n,e]*P_e (+ S3 on e==0), via REDG atomicAdd into the
// pre-zeroed output (mask-skipped rows contribute nothing; memset keeps 0).
// Block = 128 thr (4 warps); warp (wn=w&1, wc=w>>1) = 16n x 16c tile;
// per k16: ldmatrix.x4 (A) + 2 x (ldmatrix.x2.trans + mma.m16n8k16).
// Pads: A rows 272B, B rows 80B (both conflict-free ldmatrix).
// ---------------------------------------------------------------------------
#define AS_B (32 * 272)                     // 8704 B per A buffer
#define BS_B (128 * 80)                     // 10240 B per B buffer

__global__ __launch_bounds__(128) void agg_kernel(
    const int* __restrict__ mask,
    float* __restrict__ out)
{
    __shared__ __align__(16) unsigned char As[2][AS_B];
    __shared__ __align__(16) unsigned char Bs[2][BS_B];

    int t = threadIdx.x, w = t >> 5, lane = t & 31;
    int wn = w & 1, wc = w >> 1;
    int b = blockIdx.y, n0 = blockIdx.x * 32, e = blockIdx.z;

    uint32_t asb = sptr(&As[0][0]), bsb = sptr(&Bs[0][0]);
    const __nv_bfloat16* adjb = g_adjbf + ((size_t)(b * 3 + e) << 20);
    const __nv_bfloat16* sgb  = g_saggbf + ((size_t)(b * 3 + e) << 15);

    auto cpAB = [&](int buf, int i) {
        int k0 = i * 128;
        const __nv_bfloat16* Asrc = adjb + (size_t)n0 * 1024 + k0;
        uint32_t ad = asb + (uint32_t)buf * AS_B;
#pragma unroll
        for (int j = 0; j < 4; j++) {
            int g = t + 128 * j;
            int row = g >> 4, seg = g & 15;
            CPASYNC16(ad + (uint32_t)(row * 272 + seg * 16),
                      Asrc + (size_t)row * 1024 + seg * 8);
        }
        const __nv_bfloat16* Bsrc = sgb + (size_t)k0 * 32;
        uint32_t bd = bsb + (uint32_t)buf * BS_B;
#pragma unroll
        for (int j = 0; j < 4; j++) {
            int g = t + 128 * j;
            int kr = g >> 2, seg = g & 3;
            CPASYNC16(bd + (uint32_t)(kr * 80 + seg * 16),
                      Bsrc + (size_t)kr * 32 + seg * 8);
        }
        CP_COMMIT();
    };

    float acc[2][4];
#pragma unroll
    for (int f = 0; f < 2; f++)
#pragma unroll
        for (int p = 0; p < 4; p++) acc[f][p] = 0.f;

    int lrow = lane & 15, lhalf = lane >> 4;

    cpAB(0, 0);
    cpAB(1, 1);

    for (int i = 0; i < 8; i++) {
        if (i < 7) CP_WAIT1(); else CP_WAIT0();
        __syncthreads();

        uint32_t ab = asb + (uint32_t)((i & 1) * AS_B)
                    + (uint32_t)((wn * 16 + lrow) * 272 + lhalf * 16);
        uint32_t bb = bsb + (uint32_t)((i & 1) * BS_B)
                    + (uint32_t)(lrow * 80 + wc * 32);
#pragma unroll
        for (int kk = 0; kk < 8; kk++) {
            uint32_t a0, a1, a2, a3;
            asm volatile("ldmatrix.sync.aligned.m8n8.x4.shared.b16 {%0,%1,%2,%3}, [%4];"
                : "=r"(a0), "=r"(a1), "=r"(a2), "=r"(a3)
                : "r"(ab + (uint32_t)(kk * 32)));
#pragma unroll
            for (int f = 0; f < 2; f++) {
                uint32_t b0, b1;
                asm volatile("ldmatrix.sync.aligned.m8n8.x2.trans.shared.b16 {%0,%1}, [%2];"
                    : "=r"(b0), "=r"(b1)
                    : "r"(bb + (uint32_t)(kk * 16 * 80 + f * 16)));
                asm volatile(
                    "mma.sync.aligned.m16n8k16.row.col.f32.bf16.bf16.f32 "
                    "{%0,%1,%2,%3}, {%4,%5,%6,%7}, {%8,%9}, {%0,%1,%2,%3};"
                    : "+f"(acc[f][0]), "+f"(acc[f][1]), "+f"(acc[f][2]), "+f"(acc[f][3])
                    : "r"(a0), "r"(a1), "r"(a2), "r"(a3), "r"(b0), "r"(b1));
            }
        }
        __syncthreads();
        if (i < 6) cpAB(i & 1, i + 2);
    }

    // epilogue: out += dis[n,e] * P_e (+ S3 on e==0), masked, via atomicAdd
    int r0 = n0 + wn * 16 + (lane >> 2);
#pragma unroll
    for (int h = 0; h < 2; h++) {
        int r = r0 + h * 8;
        size_t rown = (size_t)b * 1024 + r;
        if (mask[rown] == 0) continue;       // contributes nothing; out stays 0
        float d = g_dis[rown * 3 + e];
#pragma unroll
        for (int f = 0; f < 2; f++) {
            int c = wc * 16 + f * 8 + 2 * (lane & 3);
            float v0 = d * acc[f][h * 2 + 0];
            float v1 = d * acc[f][h * 2 + 1];
            if (e == 0) {
                v0 += g_S3[rown * 32 + c];
                v1 += g_S3[rown * 32 + c + 1];
            }
            atomicAdd(out + rown * 32 + c,     v0);
            atomicAdd(out + rown * 32 + c + 1, v1);
        }
    }
}

// ---------------------------------------------------------------------------
extern "C" void kernel_launch(void* const* d_in, const int* in_sizes, int n_in,
                              void* d_out, int out_size)
{
    const float* x    = (const float*)d_in[0];   // [16,1024,32]
    const float* adj  = (const float*)d_in[1];   // [16,1024,1024,3]
    const int*   mask = (const int*)d_in[2];     // [16,1024] bool -> int32
    const float* W    = (const float*)d_in[3];   // [32,96]
    const float* W0   = (const float*)d_in[4];   // [32,96]
    const float* b0   = (const float*)d_in[5];   // [96]
    float*       out  = (float*)d_out;           // [16,1024,32]

    (void)in_sizes; (void)n_in;

    deg_kernel<<<Bn * Nn, 128>>>(adj, x, W, W0, b0);
    cudaMemsetAsync(d_out, 0, (size_t)out_size * sizeof(float));
    agg_kernel<<<dim3(Nn / 32, Bn, 3), 128>>>(mask, out);
}